// round 1
// baseline (speedup 1.0000x reference)
#include <cuda_runtime.h>

#define GRID_N 32
#define CELLS  1024
#define PW     34            // padded width (32 + 1 halo each side)
#define PAD_CELLS (PW * PW)  // 1156

__global__ void __launch_bounds__(1024, 1)
dijkstra_grid_kernel(const float* __restrict__ wg, float* __restrict__ out)
{
    __shared__ float dist[PAD_CELLS];
    __shared__ unsigned short pred[CELLS];
    __shared__ int changed;

    const int b = blockIdx.x;
    const int t = threadIdx.x;          // 0..1023
    const int y = t >> 5;
    const int x = t & 31;
    const int p = (y + 1) * PW + (x + 1);   // padded index of my cell
    const float INF = __int_as_float(0x7f800000);

    // cost to ENTER my cell (source-independent edge weight)
    const float wv = wg[(size_t)b * CELLS + t];

    // init: INF everywhere (incl. halo), source = 0
    for (int i = t; i < PAD_CELLS; i += 1024) dist[i] = INF;
    __syncthreads();
    if (t == 0) { dist[1 * PW + 1] = 0.0f; changed = 0; }
    __syncthreads();

    // ---- min-plus fixed point: dist[c] = w[c] + min8(neighbor dist) ----
    // In-place updates are safe: values only decrease, every value is an exact
    // float path-sum, and the unique fixed point equals the reference's
    // Dijkstra distances bit-for-bit.
    while (true) {
        float m = fminf(
            fminf(fminf(dist[p - PW - 1], dist[p - PW]),
                  fminf(dist[p - PW + 1], dist[p - 1])),
            fminf(fminf(dist[p + 1],      dist[p + PW - 1]),
                  fminf(dist[p + PW],     dist[p + PW + 1])));
        float nv = m + wv;
        if (nv < dist[p]) { dist[p] = nv; changed = 1; }

        __syncthreads();            // all updates of this pass visible
        int c = changed;            // everyone snapshots the flag
        __syncthreads();            // nobody resets before all have read
        if (!c) break;              // uniform exit — no barrier divergence
        if (t == 0) changed = 0;
        __syncthreads();
    }

    // ---- predecessor = argmin over 8 neighbor distances ----
    // (halo entries are INF, so out-of-bounds neighbors never win; strict '<'
    //  matches the reference's "first strict improvement" semantics)
    {
        const int dy[8] = {-1, 1, 0, 0, -1, -1, 1, 1};
        const int dx[8] = { 0, 0,-1, 1, -1,  1,-1, 1};
        float bd = INF;
        int py = 0, px = 0;
#pragma unroll
        for (int d = 0; d < 8; d++) {
            float dd = dist[p + dy[d] * PW + dx[d]];
            if (dd < bd) { bd = dd; py = y + dy[d]; px = x + dx[d]; }
        }
        pred[t] = (unsigned short)(py * GRID_N + px);
    }

    // ---- emit path: zero the tile, then backtrack from (31,31) to (0,0) ----
    float* ob = out + (size_t)b * CELLS;
    ob[t] = 0.0f;
    __syncthreads();                 // orders the zeros before the 1.0 marks

    if (t == 0) {
        int cur = CELLS - 1;         // (31,31)
        for (int i = 0; i < CELLS; i++) {
            ob[cur] = 1.0f;
            if (cur == 0) break;     // pred[0,0] is a fixed point in the ref
            cur = pred[cur];
        }
    }
}

extern "C" void kernel_launch(void* const* d_in, const int* in_sizes, int n_in,
                              void* d_out, int out_size)
{
    const float* w = (const float*)d_in[0];
    float* out = (float*)d_out;
    int batches = in_sizes[0] / CELLS;   // 128
    dijkstra_grid_kernel<<<batches, 1024>>>(w, out);
}

// round 2
// speedup vs baseline: 1.0077x; 1.0077x over previous
#include <cuda_runtime.h>

#define GRID_N 32
#define CELLS  1024
#define FULLMASK 0xffffffffu
#define EPOCH_SWEEPS 8

__global__ void __launch_bounds__(1024, 1)
dijkstra_grid_kernel(const float* __restrict__ wg, float* __restrict__ out)
{
    __shared__ float dist[CELLS];           // row-major 32x32, warp y owns row y
    __shared__ unsigned short pred[CELLS];
    __shared__ unsigned char  mark[CELLS];
    __shared__ int changed;

    volatile float* vs = dist;              // force real LDS/STS each sweep

    const int b = blockIdx.x;
    const int t = threadIdx.x;              // 0..1023
    const int y = t >> 5;                   // warp id = row
    const int x = t & 31;                   // lane = column
    const float INF = __int_as_float(0x7f800000);

    const float wv = wg[(size_t)b * CELLS + t];   // cost to ENTER my cell

    // init
    float dv = (t == 0) ? 0.0f : INF;       // my distance, register-resident
    dist[t] = dv;
    mark[t] = 0;
    if (t == 0) changed = 0;
    __syncthreads();

    const bool x0 = (x == 0), x31 = (x == 31);
    const bool y0 = (y == 0), y31 = (y == 31);

    // ---- chaotic min-plus relaxation, barrier-free within an epoch ----
    // Values are monotone-decreasing exact float path-sums; the unique fixed
    // point equals the reference Dijkstra distances bitwise. Termination is
    // checked once per epoch with a race-free 3-barrier flag protocol.
    int ch = 0;
    for (;;) {
#pragma unroll
        for (int k = 0; k < EPOCH_SWEEPS; k++) {
            float up = y0  ? INF : vs[t - 32];
            float dn = y31 ? INF : vs[t + 32];
            float ul = __shfl_up_sync  (FULLMASK, up, 1);
            float dl = __shfl_up_sync  (FULLMASK, dn, 1);
            float lf = __shfl_up_sync  (FULLMASK, dv, 1);
            float ur = __shfl_down_sync(FULLMASK, up, 1);
            float dr = __shfl_down_sync(FULLMASK, dn, 1);
            float rt = __shfl_down_sync(FULLMASK, dv, 1);
            if (x0)  { ul = INF; dl = INF; lf = INF; }
            if (x31) { ur = INF; dr = INF; rt = INF; }
            float m = fminf(fminf(fminf(up, dn), fminf(ul, ur)),
                            fminf(fminf(dl, dr), fminf(lf, rt)));
            m += wv;
            if (m < dv) { dv = m; vs[t] = m; ch = 1; }
        }
        if (ch) changed = 1;      // any change during this epoch
        __syncthreads();          // (1) all sets visible
        int c = changed;          // everyone snapshots
        __syncthreads();          // (2) all reads done before reset
        if (!c) break;            // uniform exit
        if (t == 0) changed = 0;
        ch = 0;
        __syncthreads();          // (3) reset ordered before next epoch's sets
    }

    // ---- predecessor = argmin over 8 neighbor distances (unique a.s.) ----
    {
        float up = y0  ? INF : dist[t - 32];
        float dn = y31 ? INF : dist[t + 32];
        float ul = __shfl_up_sync  (FULLMASK, up, 1);
        float dl = __shfl_up_sync  (FULLMASK, dn, 1);
        float lf = __shfl_up_sync  (FULLMASK, dv, 1);
        float ur = __shfl_down_sync(FULLMASK, up, 1);
        float dr = __shfl_down_sync(FULLMASK, dn, 1);
        float rt = __shfl_down_sync(FULLMASK, dv, 1);
        if (x0)  { ul = INF; dl = INF; lf = INF; }
        if (x31) { ur = INF; dr = INF; rt = INF; }

        float nb[8] = { up, dn, lf, rt, ul, ur, dl, dr };
        int   id[8] = { t - 32, t + 32, t - 1, t + 1,
                        t - 33, t - 31, t + 31, t + 33 };
        float bd = INF; int bi = 0;
#pragma unroll
        for (int i = 0; i < 8; i++)
            if (nb[i] < bd) { bd = nb[i]; bi = id[i]; }
        pred[t] = (unsigned short)bi;
    }
    __syncthreads();

    // ---- backtrack from (31,31): mark into smem (serial, short chain) ----
    if (t == 0) {
        int cur = CELLS - 1;
        for (int i = 0; i < CELLS; i++) {
            mark[cur] = 1;
            if (cur == 0) break;            // pred chain is strictly decreasing in dist
            cur = pred[cur];
        }
    }
    __syncthreads();

    // one coalesced store per thread
    out[(size_t)b * CELLS + t] = mark[t] ? 1.0f : 0.0f;
}

extern "C" void kernel_launch(void* const* d_in, const int* in_sizes, int n_in,
                              void* d_out, int out_size)
{
    const float* w = (const float*)d_in[0];
    float* out = (float*)d_out;
    int batches = in_sizes[0] / CELLS;      // 128
    dijkstra_grid_kernel<<<batches, 1024>>>(w, out);
}

// round 3
// speedup vs baseline: 1.2243x; 1.2150x over previous
#include <cuda_runtime.h>

#define GRID_N 32
#define CELLS  1024
#define PW     34               // padded width (halo of INF)
#define PAD    (PW * PW)        // 1156
#define RPT    4                // rows per thread (vertical strip)
#define NT     256              // 8 warps
#define ESW    4                // sweeps per termination check

__global__ void __launch_bounds__(NT, 1)
dijkstra_grid_kernel(const float* __restrict__ wg, float* __restrict__ out)
{
    __shared__ float dist[PAD];            // padded 34x34, halo = INF
    __shared__ unsigned short pred[CELLS];
    __shared__ unsigned char  mark[CELLS];
    __shared__ int changed;

    volatile float* vs = dist;             // real LDS/STS every access

    const int b = blockIdx.x;
    const int t = threadIdx.x;
    const int w = t >> 5;                  // warp id 0..7 -> strip of 4 rows
    const int x = t & 31;                  // lane = column
    const int y0 = w * RPT;
    const float INF = __int_as_float(0x7f800000);

    // weights (cost to ENTER cell) for my 4 cells — coalesced per row
    float wv[RPT];
#pragma unroll
    for (int r = 0; r < RPT; r++)
        wv[r] = wg[(size_t)b * CELLS + (y0 + r) * GRID_N + x];

    // init: INF everywhere incl. halo
    for (int i = t; i < PAD; i += NT) dist[i] = INF;
    for (int i = t; i < CELLS; i += NT) mark[i] = 0;
    if (t == 0) changed = 0;
    __syncthreads();

    float d[RPT];
#pragma unroll
    for (int r = 0; r < RPT; r++) d[r] = INF;
    if (t == 0) d[0] = 0.0f;               // source (0,0)

    const int p0 = (y0 + 1) * PW + (x + 1);
#pragma unroll
    for (int r = 0; r < RPT; r++) dist[p0 + r * PW] = d[r];
    __syncthreads();

    // ---- chaotic min-plus relaxation, Gauss-Seidel within each strip ----
    // All values are exact monotone-decreasing float path-sums; the unique
    // fixed point equals the reference Dijkstra distances bitwise.
    for (;;) {
        int ch = 0;
#pragma unroll
        for (int e = 0; e < ESW; e++) {
            // ---- DOWN pass (rows y0 .. y0+3), rolling lateral reuse ----
            float al = vs[p0 - PW - 1];    // up-left
            float ac = vs[p0 - PW];        // up-center
            float ar = vs[p0 - PW + 1];    // up-right
            float bl = vs[p0 - 1];         // own-left
            float br = vs[p0 + 1];         // own-right
#pragma unroll
            for (int r = 0; r < RPT; r++) {
                const int p = p0 + r * PW;
                float cl = vs[p + PW - 1];                       // down-left
                float cr = vs[p + PW + 1];                       // down-right
                float dc = (r < RPT - 1) ? d[r + 1] : vs[p + PW];// down-center
                float m = fminf(fminf(fminf(al, ac), fminf(ar, bl)),
                                fminf(fminf(br, cl), fminf(cr, dc)));
                m += wv[r];
                if (m < d[r]) { d[r] = m; vs[p] = m; ch = 1; }
                al = bl; ar = br; ac = d[r];   // roll down one row
                bl = cl; br = cr;
            }
            // ---- UP pass (rows y0+2 .. y0) ----
            {
                float l2 = vs[p0 + (RPT - 1) * PW - 1];  // laterals of bottom row
                float r2 = vs[p0 + (RPT - 1) * PW + 1];
                float c2 = d[RPT - 1];
#pragma unroll
                for (int r = RPT - 2; r >= 0; r--) {
                    const int p = p0 + r * PW;
                    float ul = vs[p - PW - 1];
                    float ur = vs[p - PW + 1];
                    float uc = (r > 0) ? d[r - 1] : vs[p - PW];
                    float ol = vs[p - 1];
                    float orr = vs[p + 1];
                    float m = fminf(fminf(fminf(ul, uc), fminf(ur, ol)),
                                    fminf(fminf(orr, l2), fminf(r2, c2)));
                    m += wv[r];
                    if (m < d[r]) { d[r] = m; vs[p] = m; ch = 1; }
                    l2 = ol; r2 = orr; c2 = d[r];
                }
            }
        }
        // race-free 3-barrier termination check
        if (ch) changed = 1;
        __syncthreads();           // (1) all flag sets visible
        int c = changed;
        __syncthreads();           // (2) all reads done before reset
        if (!c) break;             // uniform exit
        if (t == 0) changed = 0;
        __syncthreads();           // (3) reset ordered before next epoch
    }

    // ---- predecessor = argmin over 8 neighbor distances (unique a.s.) ----
#pragma unroll
    for (int r = 0; r < RPT; r++) {
        const int p = p0 + r * PW;
        const int cell = (y0 + r) * GRID_N + x;
        const int dy[8] = {-1, 1, 0, 0, -1, -1, 1, 1};
        const int dx[8] = { 0, 0,-1, 1, -1,  1,-1, 1};
        float bd = INF; int bi = 0;
#pragma unroll
        for (int k = 0; k < 8; k++) {
            float dd = dist[p + dy[k] * PW + dx[k]];
            if (dd < bd) { bd = dd; bi = (y0 + r + dy[k]) * GRID_N + (x + dx[k]); }
        }
        pred[cell] = (unsigned short)bi;
    }
    __syncthreads();

    // ---- backtrack from (31,31); pred chain strictly decreases dist ----
    if (t == 0) {
        int cur = CELLS - 1;
        for (int i = 0; i < CELLS; i++) {
            mark[cur] = 1;
            if (cur == 0) break;
            cur = pred[cur];
        }
    }
    __syncthreads();

    // ---- coalesced output: thread writes its 4 cells ----
    float* ob = out + (size_t)b * CELLS;
#pragma unroll
    for (int r = 0; r < RPT; r++) {
        const int cell = (y0 + r) * GRID_N + x;   // warp-contiguous per r
        ob[cell] = mark[cell] ? 1.0f : 0.0f;
    }
}

extern "C" void kernel_launch(void* const* d_in, const int* in_sizes, int n_in,
                              void* d_out, int out_size)
{
    const float* w = (const float*)d_in[0];
    float* out = (float*)d_out;
    int batches = in_sizes[0] / CELLS;     // 128
    dijkstra_grid_kernel<<<batches, NT>>>(w, out);
}

// round 4
// speedup vs baseline: 1.3877x; 1.1335x over previous
#include <cuda_runtime.h>

#define GRID_N 32
#define CELLS  1024
#define PW     34               // padded width (halo of INF)
#define PAD    (PW * PW)        // 1156
#define NT     512              // 16 warps, 2 rows per thread
#define ESW    4                // sweeps per termination check

__global__ void __launch_bounds__(NT, 1)
dijkstra_grid_kernel(const float* __restrict__ wg, float* __restrict__ out)
{
    __shared__ float dist[PAD];             // padded 34x34, halo = INF
    __shared__ unsigned short pred[CELLS];
    __shared__ unsigned char  mark[CELLS];
    __shared__ int flags[3];                // round-robin convergence flags

    volatile float* vs = dist;

    const int b = blockIdx.x;
    const int t = threadIdx.x;              // 0..511
    const int x = t & 31;                   // lane = column
    const int y0 = (t >> 5) * 2;            // warp owns 2 rows
    const float INF = __int_as_float(0x7f800000);

    const float w0 = wg[(size_t)b * CELLS + y0 * GRID_N + x];
    const float w1 = wg[(size_t)b * CELLS + (y0 + 1) * GRID_N + x];

    for (int i = t; i < PAD; i += NT) dist[i] = INF;
    for (int i = t; i < CELLS; i += NT) mark[i] = 0;
    if (t < 3) flags[t] = 0;
    __syncthreads();

    float d0 = (t == 0) ? 0.0f : INF;       // my two cells, register-resident
    float d1 = INF;
    const int p0 = (y0 + 1) * PW + (x + 1); // padded index of row y0 cell
    dist[p0] = d0;
    dist[p0 + PW] = d1;
    __syncthreads();

    // ---- chaotic min-plus relaxation ----
    // Every value is an exact, monotone-decreasing float path-sum; the unique
    // fixed point equals the reference Dijkstra distances bitwise.
    int e = 0;
    for (;; e++) {
        int ch = 0;
#pragma unroll
        for (int k = 0; k < ESW; k++) {
            // front-batched neighbor loads (old values — valid chaotic relax)
            float ul = vs[p0 - PW - 1];
            float uc = vs[p0 - PW];
            float ur = vs[p0 - PW + 1];
            float l0 = vs[p0 - 1];
            float r0 = vs[p0 + 1];
            float l1 = vs[p0 + PW - 1];
            float r1 = vs[p0 + PW + 1];
            float bl = vs[p0 + 2 * PW - 1];
            float bc = vs[p0 + 2 * PW];
            float br = vs[p0 + 2 * PW + 1];

            // row y0 (down-center = d1, register Gauss-Seidel)
            float m0 = fminf(fminf(fminf(ul, uc), fminf(ur, l0)),
                             fminf(fminf(r0, l1), fminf(r1, d1))) + w0;
            if (m0 < d0) { d0 = m0; vs[p0] = m0; ch = 1; }

            // row y0+1 (up-center = fresh d0)
            float m1 = fminf(fminf(fminf(l0, r0), fminf(d0, l1)),
                             fminf(fminf(r1, bl), fminf(bc, br))) + w1;
            if (m1 < d1) { d1 = m1; vs[p0 + PW] = m1; ch = 1; }

            // back-propagate fresh d1 into d0 (cheap upward GS hop)
            float m0b = d1 + w0;
            if (m0b < d0) { d0 = m0b; vs[p0] = m0b; ch = 1; }
        }
        if (ch) flags[e % 3] = 1;
        if (t == 0) flags[(e + 1) % 3] = 0;   // reset BEFORE barrier: ordered
        __syncthreads();                       // vs all reads (bar e-1) and
        if (!flags[e % 3]) break;              // all next-epoch sets (bar e)
    }

    // ---- predecessor = argmin over 8 neighbor distances (unique a.s.) ----
#pragma unroll
    for (int r = 0; r < 2; r++) {
        const int p = p0 + r * PW;
        const int cell = (y0 + r) * GRID_N + x;
        const int dy[8] = {-1, 1, 0, 0, -1, -1, 1, 1};
        const int dx[8] = { 0, 0,-1, 1, -1,  1,-1, 1};
        float bd = INF; int bi = 0;
#pragma unroll
        for (int k = 0; k < 8; k++) {
            float dd = dist[p + dy[k] * PW + dx[k]];
            if (dd < bd) { bd = dd; bi = (y0 + r + dy[k]) * GRID_N + (x + dx[k]); }
        }
        pred[cell] = (unsigned short)bi;
    }
    __syncthreads();

    // ---- backtrack from (31,31); pred chain strictly decreases dist ----
    if (t == 0) {
        int cur = CELLS - 1;
        for (int i = 0; i < CELLS; i++) {
            mark[cur] = 1;
            if (cur == 0) break;
            cur = pred[cur];
        }
    }
    __syncthreads();

    // ---- coalesced output: 2 cells per thread ----
    float* ob = out + (size_t)b * CELLS;
    {
        const int c0 = y0 * GRID_N + x;
        ob[c0] = mark[c0] ? 1.0f : 0.0f;
        const int c1 = c0 + GRID_N;
        ob[c1] = mark[c1] ? 1.0f : 0.0f;
    }
}

extern "C" void kernel_launch(void* const* d_in, const int* in_sizes, int n_in,
                              void* d_out, int out_size)
{
    const float* w = (const float*)d_in[0];
    float* out = (float*)d_out;
    int batches = in_sizes[0] / CELLS;      // 128
    dijkstra_grid_kernel<<<batches, NT>>>(w, out);
}